// round 9
// baseline (speedup 1.0000x reference)
#include <cuda_runtime.h>

#define SEQ       128
#define BATCH     512
#define INPUT_DIM 128
#define HIDDEN    128
#define NQ        8

typedef unsigned long long u64;

__device__ __forceinline__ u64 pk(float lo, float hi) {
    u64 r; asm("mov.b64 %0, {%1, %2};" : "=l"(r) : "f"(lo), "f"(hi)); return r;
}
__device__ __forceinline__ void upk(u64 v, float& lo, float& hi) {
    asm("mov.b64 {%0, %1}, %2;" : "=f"(lo), "=f"(hi) : "l"(v));
}
#define MUL2(o,a,b)   asm("mul.rn.f32x2 %0, %1, %2;"     : "=l"(o) : "l"(a), "l"(b))
#define FMA2(o,a,b,c) asm("fma.rn.f32x2 %0, %1, %2, %3;" : "=l"(o) : "l"(a), "l"(b), "l"(c))

__device__ __forceinline__ void cmul(float& orr, float& oi,
                                     float ar, float ai, float br, float bi) {
    orr = fmaf(ar, br, -ai * bi);
    oi  = fmaf(ar, bi,  ai * br);
}

__global__ __launch_bounds__(128, 4)
void qlstm_all(const float* __restrict__ inputs,  // [SEQ,BATCH,INPUT_DIM]
               const float* __restrict__ Wq,      // [32,256] rows 0..7 used
               const float* __restrict__ bq,
               const float* __restrict__ pf,
               const float* __restrict__ pi_,
               const float* __restrict__ pg,
               const float* __restrict__ po,
               const float* __restrict__ Wf, const float* __restrict__ bf,
               const float* __restrict__ Wi, const float* __restrict__ bi,
               const float* __restrict__ Wg, const float* __restrict__ bg,
               const float* __restrict__ Wo, const float* __restrict__ bo,
               float* __restrict__ out)
{
    const int b    = blockIdx.x;
    const int tid  = threadIdx.x;
    const int wid  = tid >> 5;
    const int lane = tid & 31;

    __shared__ float4 sWqX[8][32];       // 4KB : Wq row r, x-cols 4l..4l+3
    __shared__ float4 sQHa[4][32];       // 2KB : rows 0-3 coeff for h=4l+u
    __shared__ float4 sQHb[4][32];       // 2KB : rows 4-7 coeff for h=4l+u
    __shared__ float4 sWgE[NQ][4][32];   // 16KB: (Wf,Wi,Wg,Wo)*sc2 for (w, h=4l+u)
    __shared__ float4 sB4[4][32];        // 2KB : (bf,bi,bg,bo) for h=4l+u
    __shared__ float  sSc2[4];
    __shared__ u64    sKA[4][NQ], sKB[4][NQ];  // per-warp d0 constants
    __shared__ float4 zsh4[2][NQ];       // per wire: (zf,zi,zg,zo)
    __shared__ float2 qscW[4][NQ];       // per-warp (cos,sin) of q_in/2

    // ---------- per-warp gate constants ----------
    float rtau[NQ];   // tan(phi1/2), kept in registers
    {
        const float* prm = (wid == 0) ? pf : (wid == 1) ? pi_ : (wid == 2) ? pg : po;
        float prodc = 1.f;
        #pragma unroll
        for (int w = 0; w < NQ; w++) {
            float c, s;
            __sincosf(0.5f * prm[w], &s, &c);        // d0
            if (lane == 0) { sKA[wid][w] = pk(c, s); sKB[wid][w] = pk(s, c); }
            __sincosf(0.5f * prm[NQ + w], &s, &c);   // d1
            rtau[w] = s / c;
            prodc *= c;
        }
        if (lane == 0) sSc2[wid] = prodc * prodc;
    }

    // ---------- shared weight layouts (one pass each) ----------
    {
        const float4* Wq4 = (const float4*)Wq;
        for (int i = tid; i < 256; i += 128)            // rows 0..7, x-part
            sWqX[i >> 5][i & 31] = Wq4[(i >> 5) * 64 + (i & 31)];
        int h = tid;                                    // exactly one h per thread
        int u = h & 3, l = h >> 2;
        sQHa[u][l] = make_float4(Wq[0 * 256 + 128 + h], Wq[1 * 256 + 128 + h],
                                 Wq[2 * 256 + 128 + h], Wq[3 * 256 + 128 + h]);
        sQHb[u][l] = make_float4(Wq[4 * 256 + 128 + h], Wq[5 * 256 + 128 + h],
                                 Wq[6 * 256 + 128 + h], Wq[7 * 256 + 128 + h]);
        sB4[u][l]  = make_float4(bf[h], bi[h], bg[h], bo[h]);
    }
    __syncthreads();
    {
        float scf = sSc2[0], sci = sSc2[1], scg = sSc2[2], sco = sSc2[3];
        for (int i = tid; i < NQ * HIDDEN; i += 128) {
            int w = i >> 7, h = i & 127;
            int u = h & 3, l = h >> 2;
            sWgE[w][u][l] = make_float4(Wf[h * NQ + w] * scf, Wi[h * NQ + w] * sci,
                                        Wg[h * NQ + w] * scg, Wo[h * NQ + w] * sco);
        }
    }
    __syncthreads();

    const float bqr = bq[lane & 7];
    float hv[4] = {0.f, 0.f, 0.f, 0.f};
    float cv[4] = {0.f, 0.f, 0.f, 0.f};

    float4 xcur = ((const float4*)(inputs + (size_t)b * INPUT_DIM))[lane];

    for (int t = 0; t < SEQ; t++) {
        const int buf = t & 1;

        // ---- q_in: this warp computes ALL 8 rows itself ----
        float acc[8];
        #pragma unroll
        for (int r = 0; r < 8; r++) {
            float4 wx = sWqX[r][lane];
            float a = xcur.x * wx.x;
            a = fmaf(xcur.y, wx.y, a);
            a = fmaf(xcur.z, wx.z, a);
            a = fmaf(xcur.w, wx.w, a);
            acc[r] = a;
        }
        #pragma unroll
        for (int u = 0; u < 4; u++) {
            float hval = hv[u];
            float4 wa = sQHa[u][lane];
            float4 wb = sQHb[u][lane];
            acc[0] = fmaf(hval, wa.x, acc[0]);
            acc[1] = fmaf(hval, wa.y, acc[1]);
            acc[2] = fmaf(hval, wa.z, acc[2]);
            acc[3] = fmaf(hval, wa.w, acc[3]);
            acc[4] = fmaf(hval, wb.x, acc[4]);
            acc[5] = fmaf(hval, wb.y, acc[5]);
            acc[6] = fmaf(hval, wb.z, acc[6]);
            acc[7] = fmaf(hval, wb.w, acc[7]);
        }
        // 8 sums over 32 lanes in 9 shuffles; lane ends with sum of row (lane&7)
        {
            const unsigned FM = 0xffffffffu;
            int t0 = lane & 1;
            float s0 = t0 ? acc[0] : acc[1], s1 = t0 ? acc[2] : acc[3];
            float s2 = t0 ? acc[4] : acc[5], s3 = t0 ? acc[6] : acc[7];
            float r0 = __shfl_xor_sync(FM, s0, 1);
            float r1 = __shfl_xor_sync(FM, s1, 1);
            float r2 = __shfl_xor_sync(FM, s2, 1);
            float r3 = __shfl_xor_sync(FM, s3, 1);
            float w0_ = (t0 ? acc[1] : acc[0]) + r0;
            float w1_ = (t0 ? acc[3] : acc[2]) + r1;
            float w2_ = (t0 ? acc[5] : acc[4]) + r2;
            float w3_ = (t0 ? acc[7] : acc[6]) + r3;

            int t1 = (lane >> 1) & 1;
            float s4 = t1 ? w0_ : w1_, s5 = t1 ? w2_ : w3_;
            float r4 = __shfl_xor_sync(FM, s4, 2);
            float r5 = __shfl_xor_sync(FM, s5, 2);
            float x0_ = (t1 ? w1_ : w0_) + r4;
            float x1_ = (t1 ? w3_ : w2_) + r5;

            int t2 = (lane >> 2) & 1;
            float s6 = t2 ? x0_ : x1_;
            float r6 = __shfl_xor_sync(FM, s6, 4);
            float y = (t2 ? x1_ : x0_) + r6;    // row = lane & 7

            y += __shfl_xor_sync(FM, y, 8);
            y += __shfl_xor_sync(FM, y, 16);

            float qv = y + bqr;
            float sq, cq;
            __sincosf(0.5f * qv, &sq, &cq);
            if (lane < 8) qscW[wid][lane] = make_float2(cq, sq);
        }
        __syncwarp();

        // prefetch next x (off critical path)
        float4 xnext = make_float4(0.f, 0.f, 0.f, 0.f);
        if (t + 1 < SEQ)
            xnext = ((const float4*)(inputs +
                     ((size_t)(t + 1) * BATCH + b) * INPUT_DIM))[lane];

        // ---- build per-wire A/B: A=(cf*ct,sf*st), B=(sf*ct,-cf*st) ----
        #define MAKE_AB(w, Av, Bv)                                   \
            {                                                        \
                float2 cs_ = qscW[wid][w];                           \
                u64 cp_ = pk(cs_.x, cs_.y);                          \
                u64 cm_ = pk(cs_.x, -cs_.y);                         \
                MUL2(Av, sKA[wid][w], cp_);                          \
                MUL2(Bv, sKB[wid][w], cm_);                          \
            }

        // lane product over wires 4..0 (lane bit i <-> wire 4-i), tree form
        float Lr, Li;
        {
            int s0 = lane & 1, s1 = (lane >> 1) & 1;
            int s2 = (lane >> 2) & 1, s3 = (lane >> 3) & 1, s4 = (lane >> 4) & 1;
            u64 A_, B_;
            float xr, xi, yr, yi, m0r, m0i, m1r, m1i, e0r, e0i;
            MAKE_AB(4, A_, B_); upk(s0 ? B_ : A_, xr, xi);
            MAKE_AB(3, A_, B_); upk(s1 ? B_ : A_, yr, yi);
            cmul(m0r, m0i, xr, xi, yr, yi);
            MAKE_AB(2, A_, B_); upk(s2 ? B_ : A_, xr, xi);
            MAKE_AB(1, A_, B_); upk(s3 ? B_ : A_, yr, yi);
            cmul(m1r, m1i, xr, xi, yr, yi);
            cmul(e0r, e0i, m0r, m0i, m1r, m1i);
            MAKE_AB(0, A_, B_); upk(s4 ? B_ : A_, xr, xi);
            cmul(Lr, Li, e0r, e0i, xr, xi);
        }

        // T over wires 7,6 (r bits 0,1); factored LT = L*T; then x wire5 (r bit2)
        u64 st[8];
        {
            float A7r, A7i, B7r, B7i, A6r, A6i, B6r, B6i, A5r, A5i, B5r, B5i;
            u64 A_, B_;
            MAKE_AB(7, A_, B_); upk(A_, A7r, A7i); upk(B_, B7r, B7i);
            MAKE_AB(6, A_, B_); upk(A_, A6r, A6i); upk(B_, B6r, B6i);
            MAKE_AB(5, A_, B_); upk(A_, A5r, A5i); upk(B_, B5r, B5i);

            float LTr[4], LTi[4];
            #pragma unroll
            for (int j = 0; j < 4; j++) {
                float xr = (j & 1) ? B7r : A7r, xi = (j & 1) ? B7i : A7i;
                float yr = (j & 2) ? B6r : A6r, yi = (j & 2) ? B6i : A6i;
                float tr, ti;
                cmul(tr, ti, xr, xi, yr, yi);
                cmul(LTr[j], LTi[j], Lr, Li, tr, ti);
            }
            #pragma unroll
            for (int r = 0; r < 8; r++) {
                float ur = (r & 4) ? B5r : A5r, ui = (r & 4) ? B5i : A5i;
                float fr, fi;
                cmul(fr, fi, LTr[r & 3], LTi[r & 3], ur, ui);
                st[r] = pk(fr, fi);
            }
        }
        #undef MAKE_AB

        // ---- d1 RY sweep, tan-form butterflies (normalization folded into sWgE) ----
        #pragma unroll
        for (int w = 0; w < 8; w++) {
            const int p  = 7 - w;
            const float tau = rtau[w];
            const int pairMask = (p > 0) ? (3 << (p - 1)) : 1;
            const int sideMask = (0xFF << p) & 0xFF;
            const int laneXor  = pairMask >> 3;
            const int localXor = pairMask & 7;
            const int laneSide = (sideMask >> 3) & 31;
            const int rSide    = sideMask & 7;

            float base = (__popc(lane & laneSide) & 1) ? tau : -tau;
            u64 bp = pk(base, base);
            u64 bn = pk(-base, -base);

            u64 prt[8];
            #pragma unroll
            for (int r = 0; r < 8; r++) {
                u64 v = st[r ^ localXor];
                if (laneXor) v = __shfl_xor_sync(0xffffffffu, v, laneXor);
                prt[r] = v;
            }
            #pragma unroll
            for (int r = 0; r < 8; r++) {
                const int pir = __popc(r & rSide) & 1;   // compile-time
                u64 coef = pir ? bn : bp;
                FMA2(st[r], coef, prt[r], st[r]);
            }
        }

        // ---- Z expectations (tan-scaled; scale folded into weights) ----
        float prob[8];
        #pragma unroll
        for (int r = 0; r < 8; r++) {
            float re, im;
            upk(st[r], re, im);
            prob[r] = fmaf(re, re, im * im);
        }
        float u0 = prob[0] + prob[4], v0_ = prob[0] - prob[4];
        float u1 = prob[1] + prob[5], v1_ = prob[1] - prob[5];
        float u2 = prob[2] + prob[6], v2_ = prob[2] - prob[6];
        float u3 = prob[3] + prob[7], v3_ = prob[3] - prob[7];
        float SA = (u0 + u1) + (u2 + u3);
        float S1 = (u0 + u1) - (u2 + u3);
        float S2 = (v0_ + v1_) + (v2_ + v3_);
        float S0 = (v0_ - v1_) + (v2_ - v3_);

        int pA = __popc(lane & 0x0A) & 1;
        int pB = __popc(lane & 0x15) & 1;
        int pC = __popc(lane & 0x14) & 1;
        int pD = (lane >> 3) & 1;
        int pE = (lane >> 4) & 1;
        float v0 = pA ? -S0 : S0;
        float v1 = pB ? -S1 : S1;
        float v2 = pA ? -S2 : S2;
        float v3 = pB ? -SA : SA;
        float v4 = pA ? -SA : SA;
        float v5 = pC ? -SA : SA;
        float v6 = pD ? -SA : SA;
        float v7 = pE ? -SA : SA;

        {
            const unsigned FM = 0xffffffffu;
            int t0 = lane & 1;
            float s0 = t0 ? v0 : v1, s1 = t0 ? v2 : v3;
            float s2 = t0 ? v4 : v5, s3 = t0 ? v6 : v7;
            float r0 = __shfl_xor_sync(FM, s0, 1);
            float r1 = __shfl_xor_sync(FM, s1, 1);
            float r2 = __shfl_xor_sync(FM, s2, 1);
            float r3 = __shfl_xor_sync(FM, s3, 1);
            float w0_ = (t0 ? v1 : v0) + r0;
            float w1_ = (t0 ? v3 : v2) + r1;
            float w2_ = (t0 ? v5 : v4) + r2;
            float w3_ = (t0 ? v7 : v6) + r3;

            int t1 = (lane >> 1) & 1;
            float s4 = t1 ? w0_ : w1_, s5 = t1 ? w2_ : w3_;
            float r4 = __shfl_xor_sync(FM, s4, 2);
            float r5 = __shfl_xor_sync(FM, s5, 2);
            float x0_ = (t1 ? w1_ : w0_) + r4;
            float x1_ = (t1 ? w3_ : w2_) + r5;

            int t2 = (lane >> 2) & 1;
            float s6 = t2 ? x0_ : x1_;
            float r6 = __shfl_xor_sync(FM, s6, 4);
            float y = (t2 ? x1_ : x0_) + r6;    // j = lane & 7 = p

            y += __shfl_xor_sync(FM, y, 8);
            y += __shfl_xor_sync(FM, y, 16);

            if (lane < 8)
                ((float*)&zsh4[buf][0])[(7 - lane) * 4 + wid] = y;  // wire 7-p
        }
        __syncthreads();   // the ONLY block barrier per step

        // ---- epilogue: every warp updates ALL 128 units (4 per lane) ----
        #pragma unroll
        for (int u = 0; u < 4; u++) {
            float4 bb = sB4[u][lane];
            float accf = bb.x, acci = bb.y, accg = bb.z, acco = bb.w;
            #pragma unroll
            for (int w = 0; w < NQ; w++) {
                float4 zz = zsh4[buf][w];
                float4 ww = sWgE[w][u][lane];
                accf = fmaf(zz.x, ww.x, accf);
                acci = fmaf(zz.y, ww.y, acci);
                accg = fmaf(zz.z, ww.z, accg);
                acco = fmaf(zz.w, ww.w, acco);
            }
            float fg = __fdividef(1.f, 1.f + __expf(-accf));
            float ig = __fdividef(1.f, 1.f + __expf(-acci));
            float e2 = __expf(2.f * accg);
            float gg = __fdividef(e2 - 1.f, e2 + 1.f);
            float og = __fdividef(1.f, 1.f + __expf(-acco));

            cv[u] = fmaf(fg, cv[u], ig * gg);
            float e2c = __expf(2.f * cv[u]);
            hv[u] = og * __fdividef(e2c - 1.f, e2c + 1.f);
        }
        if (wid == 0)
            ((float4*)(out + (size_t)t * BATCH * HIDDEN + (size_t)b * HIDDEN))[lane]
                = make_float4(hv[0], hv[1], hv[2], hv[3]);
        xcur = xnext;
    }

    // ---- final hx, cx ----
    if (wid == 0) {
        size_t base = (size_t)SEQ * BATCH * HIDDEN;
        ((float4*)(out + base + (size_t)b * HIDDEN))[lane]
            = make_float4(hv[0], hv[1], hv[2], hv[3]);
        ((float4*)(out + base + (size_t)BATCH * HIDDEN + (size_t)b * HIDDEN))[lane]
            = make_float4(cv[0], cv[1], cv[2], cv[3]);
    }
}

extern "C" void kernel_launch(void* const* d_in, const int* in_sizes, int n_in,
                              void* d_out, int out_size)
{
    const float* inputs = (const float*)d_in[0];
    const float* Wq     = (const float*)d_in[1];
    const float* bq     = (const float*)d_in[2];
    const float* pf     = (const float*)d_in[3];
    const float* pi_    = (const float*)d_in[4];
    const float* pg     = (const float*)d_in[5];
    const float* po     = (const float*)d_in[6];
    const float* Wf     = (const float*)d_in[7];
    const float* bf     = (const float*)d_in[8];
    const float* Wi     = (const float*)d_in[9];
    const float* bi     = (const float*)d_in[10];
    const float* Wg     = (const float*)d_in[11];
    const float* bg     = (const float*)d_in[12];
    const float* Wo     = (const float*)d_in[13];
    const float* bo     = (const float*)d_in[14];
    float* out = (float*)d_out;

    qlstm_all<<<BATCH, 128>>>(inputs, Wq, bq, pf, pi_, pg, po,
                              Wf, bf, Wi, bi, Wg, bg, Wo, bo, out);
}

// round 10
// speedup vs baseline: 3.2308x; 3.2308x over previous
#include <cuda_runtime.h>

#define SEQ       128
#define BATCH     512
#define INPUT_DIM 128
#define HIDDEN    128
#define NQ        8

__global__ __launch_bounds__(128, 4)
void qlstm_all(const float* __restrict__ inputs,  // [SEQ,BATCH,INPUT_DIM]
               const float* __restrict__ Wq,      // [32,256] rows 0..7 used
               const float* __restrict__ bq,
               const float* __restrict__ pf,
               const float* __restrict__ pi_,
               const float* __restrict__ pg,
               const float* __restrict__ po,
               const float* __restrict__ Wf, const float* __restrict__ bf,
               const float* __restrict__ Wi, const float* __restrict__ bi,
               const float* __restrict__ Wg, const float* __restrict__ bg,
               const float* __restrict__ Wo, const float* __restrict__ bo,
               float* __restrict__ out)
{
    const int b    = blockIdx.x;
    const int tid  = threadIdx.x;
    const int wid  = tid >> 5;
    const int lane = tid & 31;

    __shared__ float4 sWq4[512];            // 8KB: rows 0..7 of Wq as float4
    __shared__ float4 sWg4[NQ][HIDDEN];     // 16KB: raw (Wf,Wi,Wg,Wo) per (wire,hidden)
    __shared__ float  sBq[8];
    __shared__ float4 comb4[2][64];         // double-buffered [x;h]
    __shared__ float2 sCS[2][8];            // (cos th, sin th) FULL angle per wire
    __shared__ float4 zsh4[2][NQ];          // per wire: (zf,zi,zg,zo)

    // ---------- one-time setup ----------
    // Per-thread gate constants (FULL angles), kept in registers (unrolled idx):
    //   Cg/Sg = cos/sin(phi0_w)  [d0 layer],  cg/sg = cos/sin(phi1_w)  [d1 layer]
    float Cg[NQ], Sg[NQ], cg[NQ], sg[NQ];
    {
        const float4* Wq4 = (const float4*)Wq;
        for (int i = tid; i < 512; i += 128) sWq4[i] = Wq4[i];
        for (int i = tid; i < HIDDEN * NQ; i += 128) {
            int h = i >> 3, w = i & 7;
            sWg4[w][h] = make_float4(Wf[i], Wi[i], Wg[i], Wo[i]);
        }
        if (tid < 8) sBq[tid] = bq[tid];

        const float* prm = (wid == 0) ? pf : (wid == 1) ? pi_ : (wid == 2) ? pg : po;
        #pragma unroll
        for (int w = 0; w < NQ; w++) {
            __sincosf(prm[w],      &Sg[w], &Cg[w]);   // full angle
            __sincosf(prm[NQ + w], &sg[w], &cg[w]);   // full angle
        }
    }

    const float bfr = bf[tid], bir = bi[tid], bgr = bg[tid], bor = bo[tid];

    float hreg = 0.f, creg = 0.f;
    const float* inb = inputs + (size_t)b * INPUT_DIM;
    float xcur = inb[tid];                 // prefetch t=0
    __syncthreads();

    const int v = lane & 7;                // this lane's output wire (DP target)

    for (int t = 0; t < SEQ; t++) {
        const int buf = t & 1;

        {
            float* combS = (float*)comb4[buf];
            combS[tid]       = xcur;
            combS[128 + tid] = hreg;
        }
        float xnext = 0.f;
        if (t + 1 < SEQ) xnext = inb[(size_t)(t + 1) * BATCH * INPUT_DIM + tid];
        __syncthreads();   // A: comb visible

        // ---- q_in = combined @ Wq[:8].T + bq ; producers publish full-angle sincos ----
        {
            const float4* w0 = sWq4 + (2 * wid) * 64;
            const float4* w1 = w0 + 64;
            float4 c0 = comb4[buf][lane];
            float4 c1 = comb4[buf][32 + lane];
            float4 wa = w0[lane], wb = w0[32 + lane];
            float4 wc = w1[lane], wd = w1[32 + lane];
            float a0 = c0.x * wa.x;
            a0 = fmaf(c0.y, wa.y, a0); a0 = fmaf(c0.z, wa.z, a0); a0 = fmaf(c0.w, wa.w, a0);
            a0 = fmaf(c1.x, wb.x, a0); a0 = fmaf(c1.y, wb.y, a0);
            a0 = fmaf(c1.z, wb.z, a0); a0 = fmaf(c1.w, wb.w, a0);
            float a1 = c0.x * wc.x;
            a1 = fmaf(c0.y, wc.y, a1); a1 = fmaf(c0.z, wc.z, a1); a1 = fmaf(c0.w, wc.w, a1);
            a1 = fmaf(c1.x, wd.x, a1); a1 = fmaf(c1.y, wd.y, a1);
            a1 = fmaf(c1.z, wd.z, a1); a1 = fmaf(c1.w, wd.w, a1);
            const unsigned FM = 0xffffffffu;
            int t0 = lane & 1;
            float s  = t0 ? a0 : a1;
            float rr = __shfl_xor_sync(FM, s, 1);
            float vsum = (t0 ? a1 : a0) + rr;
            #pragma unroll
            for (int o = 2; o <= 16; o <<= 1) vsum += __shfl_xor_sync(FM, vsum, o);
            if (lane < 2) {
                float qv = vsum + sBq[2 * wid + lane];
                float sq, cq;
                __sincosf(qv, &sq, &cq);             // FULL angle
                sCS[buf][2 * wid + lane] = make_float2(cq, sq);
            }
        }
        __syncthreads();   // B: sCS visible

        // ---- Heisenberg DP: z_v = <psi0| prod_{i<=v} [cg_i Z0..Zi - sg_i Xi X_{i+1}] |psi0>
        // Per-wire stats: zeta = Cg*cos(th), x = Sg*cos(th), y = -sin(th), <XZ> = -i*y.
        // DP state (P = Z-parity of decided c's, L = last choice was X), complex values.
        float W00r = 1.f, W00i = 0.f, W10r = 0.f, W10i = 0.f;
        float W01r = 0.f, W01i = 0.f, W11r = 0.f, W11i = 0.f;

        #pragma unroll
        for (int j = 7; j >= 0; j--) {
            float zf, xf, yf;
            if (j == 7) { zf = 0.f; xf = 1.f; yf = 0.f; }   // virtual wire 8: only F(1,0)=1 used
            else {
                float2 cs = sCS[buf][j + 1];
                zf = Cg[j + 1] * cs.x;
                xf = Sg[j + 1] * cs.x;
                yf = -cs.y;
            }
            if (j <= v) {
                float cj = cg[j], sj = sg[j];
                // Z-branch: target (P^1, 0), factor F(L, P)
                float n10r = cj * fmaf(W01r, xf, W00r);
                float n10i = cj * fmaf(W01i, xf, W00i);
                float n00r = cj * fmaf(W11i,  yf, W10r * zf);
                float n00i = cj * fmaf(-W11r, yf, W10i * zf);
                // X-branch: target (P, 1), factor F(L^1, P)
                float n01r = -sj * fmaf(W00r, xf, W01r);
                float n01i = -sj * fmaf(W00i, xf, W01i);
                float n11r = -sj * fmaf(W10i,  yf, W11r * zf);
                float n11i = -sj * fmaf(-W10r, yf, W11i * zf);
                W00r = n00r; W00i = n00i; W10r = n10r; W10i = n10i;
                W01r = n01r; W01i = n01i; W11r = n11r; W11i = n11i;
            }
        }
        // closure with wire-0 stats: E = W00 + x0*W01 + z0*W10 + y0*Im(W11)
        {
            float2 cs0 = sCS[buf][0];
            float zf0 = Cg[0] * cs0.x;
            float xf0 = Sg[0] * cs0.x;
            float yf0 = -cs0.y;
            float E = W00r;
            E = fmaf(xf0, W01r, E);
            E = fmaf(zf0, W10r, E);
            E = fmaf(yf0, W11i, E);
            if (lane < 8)
                ((float*)&zsh4[buf][0])[lane * 4 + wid] = E;   // wire = lane, gate = wid
        }
        __syncthreads();   // C: zsh visible

        // ---- gate projections + LSTM update (thread tid <-> hidden unit tid) ----
        {
            float accf = bfr, acci = bir, accg = bgr, acco = bor;
            #pragma unroll
            for (int w = 0; w < NQ; w++) {
                float4 zz = zsh4[buf][w];
                float4 ww = sWg4[w][tid];
                accf = fmaf(zz.x, ww.x, accf);
                acci = fmaf(zz.y, ww.y, acci);
                accg = fmaf(zz.z, ww.z, accg);
                acco = fmaf(zz.w, ww.w, acco);
            }
            float fg = __fdividef(1.f, 1.f + __expf(-accf));
            float ig = __fdividef(1.f, 1.f + __expf(-acci));
            float e2 = __expf(2.f * accg);
            float gg = __fdividef(e2 - 1.f, e2 + 1.f);
            float og = __fdividef(1.f, 1.f + __expf(-acco));

            creg = fmaf(fg, creg, ig * gg);
            float e2c = __expf(2.f * creg);
            hreg = og * __fdividef(e2c - 1.f, e2c + 1.f);

            out[(size_t)t * BATCH * HIDDEN + (size_t)b * HIDDEN + tid] = hreg;
        }
        xcur = xnext;
        // no tail sync: next iteration uses the other buffer
    }

    // ---- final hx, cx ----
    size_t base = (size_t)SEQ * BATCH * HIDDEN;
    out[base + (size_t)b * HIDDEN + tid] = hreg;
    out[base + (size_t)BATCH * HIDDEN + (size_t)b * HIDDEN + tid] = creg;
}

extern "C" void kernel_launch(void* const* d_in, const int* in_sizes, int n_in,
                              void* d_out, int out_size)
{
    const float* inputs = (const float*)d_in[0];
    const float* Wq     = (const float*)d_in[1];
    const float* bq     = (const float*)d_in[2];
    const float* pf     = (const float*)d_in[3];
    const float* pi_    = (const float*)d_in[4];
    const float* pg     = (const float*)d_in[5];
    const float* po     = (const float*)d_in[6];
    const float* Wf     = (const float*)d_in[7];
    const float* bf     = (const float*)d_in[8];
    const float* Wi     = (const float*)d_in[9];
    const float* bi     = (const float*)d_in[10];
    const float* Wg     = (const float*)d_in[11];
    const float* bg     = (const float*)d_in[12];
    const float* Wo     = (const float*)d_in[13];
    const float* bo     = (const float*)d_in[14];
    float* out = (float*)d_out;

    qlstm_all<<<BATCH, 128>>>(inputs, Wq, bq, pf, pi_, pg, po,
                              Wf, bf, Wi, bi, Wg, bg, Wo, bo, out);
}